// round 1
// baseline (speedup 1.0000x reference)
#include <cuda_runtime.h>
#include <math.h>

#define D   768
#define H   12
#define HD  64
#define B1  2048
#define B2  8192

// Scratch (allocation-free rule: __device__ globals)
__device__ float g_Q[B1 * D];
__device__ float g_K[B2 * D];
__device__ float g_V[B2 * D];
__device__ float g_O[B1 * D];

__device__ __forceinline__ float decode_scalar(const void* p) {
    // invt may arrive as int32 or float32; 20 as int is small, 20.0f's bit
    // pattern as int is huge — disambiguate by magnitude.
    int iv = *(const int*)p;
    if (iv >= -1000000 && iv <= 1000000) return (float)iv;
    return *(const float*)p;
}

// ---------------------------------------------------------------------------
// C[M,N] = A[M,K] * B[N,K]^T   (128x128 tile, 8x8 per thread, 256 threads)
// Assumes M%128==0, N%128==0, K%16==0 (true for all calls here).
// ---------------------------------------------------------------------------
__global__ __launch_bounds__(256) void gemm_nt_kernel(
    const float* __restrict__ A, const float* __restrict__ B,
    float* __restrict__ C, int M, int N, int K)
{
    __shared__ float As[16][128];
    __shared__ float Bs[16][128];

    const int tid = threadIdx.x;
    const int tx = tid & 15, ty = tid >> 4;
    const int m0 = blockIdx.y * 128, n0 = blockIdx.x * 128;

    float acc[8][8];
    #pragma unroll
    for (int i = 0; i < 8; i++)
        #pragma unroll
        for (int j = 0; j < 8; j++) acc[i][j] = 0.f;

    for (int k0 = 0; k0 < K; k0 += 16) {
        #pragma unroll
        for (int t = tid; t < 512; t += 256) {
            int r = t >> 2, c = t & 3;
            float4 v = *(const float4*)(A + (size_t)(m0 + r) * K + k0 + c * 4);
            As[c*4+0][r] = v.x; As[c*4+1][r] = v.y;
            As[c*4+2][r] = v.z; As[c*4+3][r] = v.w;
        }
        #pragma unroll
        for (int t = tid; t < 512; t += 256) {
            int r = t >> 2, c = t & 3;
            float4 v = *(const float4*)(B + (size_t)(n0 + r) * K + k0 + c * 4);
            Bs[c*4+0][r] = v.x; Bs[c*4+1][r] = v.y;
            Bs[c*4+2][r] = v.z; Bs[c*4+3][r] = v.w;
        }
        __syncthreads();

        #pragma unroll
        for (int kk = 0; kk < 16; kk++) {
            float a[8], b[8];
            *(float4*)&a[0] = *(const float4*)&As[kk][ty*8];
            *(float4*)&a[4] = *(const float4*)&As[kk][ty*8+4];
            *(float4*)&b[0] = *(const float4*)&Bs[kk][tx*8];
            *(float4*)&b[4] = *(const float4*)&Bs[kk][tx*8+4];
            #pragma unroll
            for (int i = 0; i < 8; i++)
                #pragma unroll
                for (int j = 0; j < 8; j++)
                    acc[i][j] = fmaf(a[i], b[j], acc[i][j]);
        }
        __syncthreads();
    }

    #pragma unroll
    for (int i = 0; i < 8; i++) {
        int row = m0 + ty*8 + i;
        float4* cp = (float4*)(C + (size_t)row * N + n0 + tx*8);
        cp[0] = make_float4(acc[i][0], acc[i][1], acc[i][2], acc[i][3]);
        cp[1] = make_float4(acc[i][4], acc[i][5], acc[i][6], acc[i][7]);
    }
}

// ---------------------------------------------------------------------------
// Per-head L2 norm: X[rows, 768], normalize each 64-wide head chunk.
// Block = 768 threads (one per element of a row).
// ---------------------------------------------------------------------------
__global__ __launch_bounds__(768) void headnorm_kernel(float* __restrict__ X)
{
    const int row = blockIdx.x;
    const int t = threadIdx.x;           // 0..767
    float v = X[(size_t)row * D + t];
    float s = v * v;
    #pragma unroll
    for (int o = 16; o; o >>= 1) s += __shfl_xor_sync(0xffffffffu, s, o);
    __shared__ float ws[24];
    if ((t & 31) == 0) ws[t >> 5] = s;
    __syncthreads();
    int head = t >> 6;                   // 2 warps per head
    float sum = ws[head * 2] + ws[head * 2 + 1];
    float scale = 1.0f / fmaxf(sqrtf(sum), 1e-12f);
    X[(size_t)row * D + t] = v * scale;
}

// ---------------------------------------------------------------------------
// Flash attention: one block per (64-row q tile, head). 256 threads,
// 4x4 S elements per thread, online softmax, PV accumulated in registers.
// Dynamic smem: Qs[64d][64q] + Ks[64d][64k] + Vs[64k][64d] + Ps[64k][68q]
// ---------------------------------------------------------------------------
__global__ __launch_bounds__(256) void attn_kernel(
    const float* __restrict__ Q, const float* __restrict__ K,
    const float* __restrict__ V, float* __restrict__ O,
    const void* __restrict__ invt_raw)
{
    extern __shared__ float sm[];
    float* Qs = sm;            // [64][64], d-major: Qs[d*64+q]
    float* Ks = sm + 4096;     // [64][64], d-major: Ks[d*64+k]
    float* Vs = sm + 8192;     // [64][64], k-major: Vs[k*64+d]
    float* Ps = sm + 12288;    // [64][68], k-major: Ps[k*68+q]

    const int tid = threadIdx.x;
    const int tx = tid & 15, ty = tid >> 4;
    const int h = blockIdx.y;
    const int q0 = blockIdx.x * 64;
    const float invt = decode_scalar(invt_raw);

    // Load Q tile transposed into Qs[d][q]
    {
        int r = tid & 63;            // q row
        int cbase = tid >> 6;        // 0..3
        #pragma unroll
        for (int k = 0; k < 4; k++) {
            int c = cbase + k * 4;   // float4 index along d
            float4 v = *(const float4*)(Q + (size_t)(q0 + r) * D + h * HD + c * 4);
            Qs[(c*4+0)*64 + r] = v.x;
            Qs[(c*4+1)*64 + r] = v.y;
            Qs[(c*4+2)*64 + r] = v.z;
            Qs[(c*4+3)*64 + r] = v.w;
        }
    }

    float m[4], l[4], o[4][4];
    #pragma unroll
    for (int i = 0; i < 4; i++) {
        m[i] = -1e30f; l[i] = 0.f;
        #pragma unroll
        for (int j = 0; j < 4; j++) o[i][j] = 0.f;
    }
    __syncthreads();

    for (int n0 = 0; n0 < B2; n0 += 64) {
        // K tile transposed into Ks[d][k]
        {
            int r = tid & 63;
            int cbase = tid >> 6;
            #pragma unroll
            for (int k = 0; k < 4; k++) {
                int c = cbase + k * 4;
                float4 v = *(const float4*)(K + (size_t)(n0 + r) * D + h * HD + c * 4);
                Ks[(c*4+0)*64 + r] = v.x;
                Ks[(c*4+1)*64 + r] = v.y;
                Ks[(c*4+2)*64 + r] = v.z;
                Ks[(c*4+3)*64 + r] = v.w;
            }
        }
        // V tile natural layout Vs[k][d]
        {
            #pragma unroll
            for (int t = 0; t < 4; t++) {
                int idx = tid + t * 256;
                int r = idx >> 4, c = idx & 15;
                float4 v = *(const float4*)(V + (size_t)(n0 + r) * D + h * HD + c * 4);
                *(float4*)&Vs[r * 64 + c * 4] = v;
            }
        }
        __syncthreads();

        // S = Q . K^T
        float s[4][4];
        #pragma unroll
        for (int i = 0; i < 4; i++)
            #pragma unroll
            for (int j = 0; j < 4; j++) s[i][j] = 0.f;

        #pragma unroll 8
        for (int kk = 0; kk < 64; kk++) {
            float4 a4 = *(const float4*)&Qs[kk*64 + ty*4];
            float4 b4 = *(const float4*)&Ks[kk*64 + tx*4];
            float av[4] = {a4.x, a4.y, a4.z, a4.w};
            float bv[4] = {b4.x, b4.y, b4.z, b4.w};
            #pragma unroll
            for (int i = 0; i < 4; i++)
                #pragma unroll
                for (int j = 0; j < 4; j++)
                    s[i][j] = fmaf(av[i], bv[j], s[i][j]);
        }

        // scale + online softmax (rows shared by the 16 tx lanes of each ty)
        #pragma unroll
        for (int i = 0; i < 4; i++) {
            float rmax = fmaxf(fmaxf(s[i][0]*invt, s[i][1]*invt),
                               fmaxf(s[i][2]*invt, s[i][3]*invt));
            #pragma unroll
            for (int off = 1; off <= 8; off <<= 1)
                rmax = fmaxf(rmax, __shfl_xor_sync(0xffffffffu, rmax, off));
            float mn = fmaxf(m[i], rmax);
            float corr = __expf(m[i] - mn);
            m[i] = mn;
            float su = 0.f;
            #pragma unroll
            for (int j = 0; j < 4; j++) {
                s[i][j] = __expf(s[i][j]*invt - mn);
                su += s[i][j];
            }
            #pragma unroll
            for (int off = 1; off <= 8; off <<= 1)
                su += __shfl_xor_sync(0xffffffffu, su, off);
            l[i] = l[i] * corr + su;
            #pragma unroll
            for (int j = 0; j < 4; j++) o[i][j] *= corr;
        }

        // store P transposed: Ps[k][q], float4 along q
        #pragma unroll
        for (int j = 0; j < 4; j++) {
            int kc = tx*4 + j;
            float4 pv = make_float4(s[0][j], s[1][j], s[2][j], s[3][j]);
            *(float4*)&Ps[kc*68 + ty*4] = pv;
        }
        __syncthreads();

        // O += P . V
        #pragma unroll 8
        for (int kk = 0; kk < 64; kk++) {
            float4 a4 = *(const float4*)&Ps[kk*68 + ty*4];
            float4 b4 = *(const float4*)&Vs[kk*64 + tx*4];
            float av[4] = {a4.x, a4.y, a4.z, a4.w};
            float bv[4] = {b4.x, b4.y, b4.z, b4.w};
            #pragma unroll
            for (int i = 0; i < 4; i++)
                #pragma unroll
                for (int j = 0; j < 4; j++)
                    o[i][j] = fmaf(av[i], bv[j], o[i][j]);
        }
        __syncthreads();
    }

    // epilogue: O / l
    #pragma unroll
    for (int i = 0; i < 4; i++) {
        float inv = 1.0f / l[i];
        int qr = q0 + ty*4 + i;
        float4 v = make_float4(o[i][0]*inv, o[i][1]*inv, o[i][2]*inv, o[i][3]*inv);
        *(float4*)(O + (size_t)qr * D + h*HD + tx*4) = v;
    }
}

// ---------------------------------------------------------------------------
// Full-row L2 norm of X[2048, 768], in place.
// ---------------------------------------------------------------------------
__global__ __launch_bounds__(256) void rownorm_kernel(float* __restrict__ X)
{
    const int row = blockIdx.x;
    const int t = threadIdx.x;
    float* xr = X + (size_t)row * D;
    float s = 0.f;
    for (int i = t; i < D; i += 256) { float v = xr[i]; s += v * v; }
    #pragma unroll
    for (int o = 16; o; o >>= 1) s += __shfl_xor_sync(0xffffffffu, s, o);
    __shared__ float red[8];
    if ((t & 31) == 0) red[t >> 5] = s;
    __syncthreads();
    float tot = 0.f;
    #pragma unroll
    for (int i = 0; i < 8; i++) tot += red[i];
    float scale = 1.0f / fmaxf(sqrtf(tot), 1e-12f);
    for (int i = t; i < D; i += 256) xr[i] *= scale;
}

// ---------------------------------------------------------------------------
extern "C" void kernel_launch(void* const* d_in, const int* in_sizes, int n_in,
                              void* d_out, int out_size)
{
    (void)in_sizes; (void)n_in; (void)out_size;
    const float* x1 = (const float*)d_in[0];
    const float* x2 = (const float*)d_in[1];
    const float* Wq = (const float*)d_in[2];
    const float* Wk = (const float*)d_in[3];
    const float* Wv = (const float*)d_in[4];
    const float* Wo = (const float*)d_in[5];
    const void*  invt = d_in[6];
    float* out = (float*)d_out;

    void *pQ, *pK, *pV, *pO;
    cudaGetSymbolAddress(&pQ, g_Q);
    cudaGetSymbolAddress(&pK, g_K);
    cudaGetSymbolAddress(&pV, g_V);
    cudaGetSymbolAddress(&pO, g_O);

    // Projections
    gemm_nt_kernel<<<dim3(D/128, B1/128), 256>>>(x1, Wq, (float*)pQ, B1, D, D);
    gemm_nt_kernel<<<dim3(D/128, B2/128), 256>>>(x2, Wk, (float*)pK, B2, D, D);
    gemm_nt_kernel<<<dim3(D/128, B2/128), 256>>>(x2, Wv, (float*)pV, B2, D, D);

    // Per-head cosine normalization
    headnorm_kernel<<<B1, 768>>>((float*)pQ);
    headnorm_kernel<<<B2, 768>>>((float*)pK);

    // Flash attention
    const int smem_bytes = (4096 * 3 + 64 * 68) * sizeof(float);  // 66560 B
    cudaFuncSetAttribute(attn_kernel,
                         cudaFuncAttributeMaxDynamicSharedMemorySize, smem_bytes);
    attn_kernel<<<dim3(B1/64, H), 256, smem_bytes>>>(
        (float*)pQ, (float*)pK, (float*)pV, (float*)pO, invt);

    // Output projection straight into d_out, then in-place row norm
    gemm_nt_kernel<<<dim3(D/128, B1/128), 256>>>((float*)pO, Wo, out, B1, D, D);
    rownorm_kernel<<<B1, 256>>>(out);
}

// round 3
// speedup vs baseline: 1.8157x; 1.8157x over previous
#include <cuda_runtime.h>
#include <cuda_bf16.h>
#include <math.h>
#include <stdint.h>

#define D   768
#define H   12
#define HD  64
#define B1  2048
#define B2  8192

// Scratch (allocation-free rule: __device__ globals)
__device__ float g_Q[B1 * D];
__device__ float g_K[B2 * D];
__device__ float g_V[B2 * D];
__device__ float g_O[B1 * D];

__device__ __forceinline__ float decode_scalar(const void* p) {
    int iv = *(const int*)p;
    if (iv >= -1000000 && iv <= 1000000) return (float)iv;
    return *(const float*)p;
}

// Split two floats into packed bf16x2 hi + lo (residual) words.
// Packed word: low 16 bits = element 0, high 16 bits = element 1.
__device__ __forceinline__ void split2(float x0, float x1,
                                       uint32_t& hi, uint32_t& lo) {
    uint32_t h;
    asm("cvt.rn.bf16x2.f32 %0, %1, %2;" : "=r"(h) : "f"(x1), "f"(x0));
    float r0 = x0 - __uint_as_float(h << 16);
    float r1 = x1 - __uint_as_float(h & 0xffff0000u);
    uint32_t l;
    asm("cvt.rn.bf16x2.f32 %0, %1, %2;" : "=r"(l) : "f"(r1), "f"(r0));
    hi = h; lo = l;
}

__device__ __forceinline__ void split4(float4 v, uint2& hi, uint2& lo) {
    split2(v.x, v.y, hi.x, lo.x);
    split2(v.z, v.w, hi.y, lo.y);
}

// m16n8k16 bf16 mma, fp32 accumulate
__device__ __forceinline__ void mma_bf16(float c[4], const uint32_t a[4],
                                         const uint32_t b[2]) {
    asm volatile(
        "mma.sync.aligned.m16n8k16.row.col.f32.bf16.bf16.f32 "
        "{%0,%1,%2,%3}, {%4,%5,%6,%7}, {%8,%9}, {%0,%1,%2,%3};"
        : "+f"(c[0]), "+f"(c[1]), "+f"(c[2]), "+f"(c[3])
        : "r"(a[0]), "r"(a[1]), "r"(a[2]), "r"(a[3]), "r"(b[0]), "r"(b[1]));
}

// ---------------------------------------------------------------------------
// C[M,N] = A[M,K] * B[N,K]^T via bf16x3 emulated fp32 mma.
// Block tile 128x128, 8 warps (2x4), warp tile 64x32. K chunk 32 floats.
// ---------------------------------------------------------------------------
#define WS 18   // words per 32-float row chunk (16 + 2 pad)
__global__ __launch_bounds__(256) void gemm_b16x3_kernel(
    const float* __restrict__ A, const float* __restrict__ B,
    float* __restrict__ C, int M, int N, int K)
{
    __shared__ uint32_t Ah[128 * WS], Al[128 * WS];
    __shared__ uint32_t Bh[128 * WS], Bl[128 * WS];

    const int tid = threadIdx.x;
    const int w = tid >> 5, lane = tid & 31;
    const int g = lane >> 2, t = lane & 3;
    const int mw = w >> 2, nw = w & 3;      // 2 x 4 warp grid
    const int m0 = blockIdx.y * 128, n0 = blockIdx.x * 128;

    float acc[4][4][4];
    #pragma unroll
    for (int mi = 0; mi < 4; mi++)
        #pragma unroll
        for (int ni = 0; ni < 4; ni++)
            #pragma unroll
            for (int e = 0; e < 4; e++) acc[mi][ni][e] = 0.f;

    for (int k0 = 0; k0 < K; k0 += 32) {
        #pragma unroll
        for (int p = 0; p < 4; p++) {
            int idx = tid + p * 256;        // 1024 float4 = 128 rows x 8
            int r = idx >> 3, c4 = idx & 7;
            float4 v = *(const float4*)(A + (size_t)(m0 + r) * K + k0 + c4 * 4);
            uint2 hi, lo; split4(v, hi, lo);
            *(uint2*)&Ah[r * WS + c4 * 2] = hi;
            *(uint2*)&Al[r * WS + c4 * 2] = lo;
        }
        #pragma unroll
        for (int p = 0; p < 4; p++) {
            int idx = tid + p * 256;
            int r = idx >> 3, c4 = idx & 7;
            float4 v = *(const float4*)(B + (size_t)(n0 + r) * K + k0 + c4 * 4);
            uint2 hi, lo; split4(v, hi, lo);
            *(uint2*)&Bh[r * WS + c4 * 2] = hi;
            *(uint2*)&Bl[r * WS + c4 * 2] = lo;
        }
        __syncthreads();

        #pragma unroll
        for (int ks = 0; ks < 2; ks++) {
            int kw = ks * 8;
            uint32_t ah[4][4], al[4][4];
            #pragma unroll
            for (int mi = 0; mi < 4; mi++) {
                int r = mw * 64 + mi * 16 + g;
                ah[mi][0] = Ah[r * WS + kw + t];
                ah[mi][1] = Ah[(r + 8) * WS + kw + t];
                ah[mi][2] = Ah[r * WS + kw + t + 4];
                ah[mi][3] = Ah[(r + 8) * WS + kw + t + 4];
                al[mi][0] = Al[r * WS + kw + t];
                al[mi][1] = Al[(r + 8) * WS + kw + t];
                al[mi][2] = Al[r * WS + kw + t + 4];
                al[mi][3] = Al[(r + 8) * WS + kw + t + 4];
            }
            #pragma unroll
            for (int ni = 0; ni < 4; ni++) {
                int n = nw * 32 + ni * 8 + g;
                uint32_t bh[2], bl[2];
                bh[0] = Bh[n * WS + kw + t];
                bh[1] = Bh[n * WS + kw + t + 4];
                bl[0] = Bl[n * WS + kw + t];
                bl[1] = Bl[n * WS + kw + t + 4];
                #pragma unroll
                for (int mi = 0; mi < 4; mi++) {
                    mma_bf16(acc[mi][ni], ah[mi], bh);
                    mma_bf16(acc[mi][ni], ah[mi], bl);
                    mma_bf16(acc[mi][ni], al[mi], bh);
                }
            }
        }
        __syncthreads();
    }

    #pragma unroll
    for (int mi = 0; mi < 4; mi++) {
        int r0 = m0 + mw * 64 + mi * 16 + g;
        #pragma unroll
        for (int ni = 0; ni < 4; ni++) {
            int c = n0 + nw * 32 + ni * 8 + 2 * t;
            *(float2*)&C[(size_t)r0 * N + c]       = make_float2(acc[mi][ni][0], acc[mi][ni][1]);
            *(float2*)&C[(size_t)(r0 + 8) * N + c] = make_float2(acc[mi][ni][2], acc[mi][ni][3]);
        }
    }
}

// ---------------------------------------------------------------------------
// Per-head L2 norm: X[rows, 768], 64-wide head chunks.
// ---------------------------------------------------------------------------
__global__ __launch_bounds__(768) void headnorm_kernel(float* __restrict__ X)
{
    const int row = blockIdx.x;
    const int t = threadIdx.x;
    float v = X[(size_t)row * D + t];
    float s = v * v;
    #pragma unroll
    for (int o = 16; o; o >>= 1) s += __shfl_xor_sync(0xffffffffu, s, o);
    __shared__ float ws[24];
    if ((t & 31) == 0) ws[t >> 5] = s;
    __syncthreads();
    int head = t >> 6;
    float sum = ws[head * 2] + ws[head * 2 + 1];
    float scale = 1.0f / fmaxf(sqrtf(sum), 1e-12f);
    X[(size_t)row * D + t] = v * scale;
}

// ---------------------------------------------------------------------------
// Flash attention via bf16x3 mma. Block: 64 q rows x 1 head. 8 warps
// in a 4x2 grid over the 64x64 S tile (16x32 per warp). No max subtraction
// (logits bounded by |invt|). fp32 accumulate throughout.
// ---------------------------------------------------------------------------
#define VS 36   // words per 64-float row (32 + 4 pad)
__global__ __launch_bounds__(256) void attn_kernel(
    const float* __restrict__ Q, const float* __restrict__ K,
    const float* __restrict__ V, float* __restrict__ O,
    const void* __restrict__ invt_raw)
{
    extern __shared__ uint32_t sm[];
    uint32_t* Qh = sm;                 // [64 q][VS]  pairs along d
    uint32_t* Ql = Qh + 64 * VS;
    uint32_t* Kh = Ql + 64 * VS;       // [64 key][VS] pairs along d
    uint32_t* Kl = Kh + 64 * VS;
    uint32_t* Vh = Kl + 64 * VS;       // [64 d][VS] pairs along key (transposed)
    uint32_t* Vl = Vh + 64 * VS;
    uint32_t* Ph = Vl + 64 * VS;       // [64 q][VS] pairs along key
    uint32_t* Pl = Ph + 64 * VS;
    float*    part = (float*)(Pl + 64 * VS);   // [8][16] row-sum partials

    const int tid = threadIdx.x;
    const int w = tid >> 5, lane = tid & 31;
    const int g = lane >> 2, t = lane & 3;
    const int mw = w >> 1, nw = w & 1;            // 4 x 2 warp grid
    const int h = blockIdx.y;
    const int q0 = blockIdx.x * 64;
    const float invt = decode_scalar(invt_raw);

    // Load + split Q tile [q][d]
    #pragma unroll
    for (int p = 0; p < 4; p++) {
        int idx = tid + p * 256;          // 1024 float4 = 64 rows x 16
        int r = idx >> 4, c4 = idx & 15;
        float4 v = *(const float4*)(Q + (size_t)(q0 + r) * D + h * HD + c4 * 4);
        uint2 hi, lo; split4(v, hi, lo);
        *(uint2*)&Qh[r * VS + c4 * 2] = hi;
        *(uint2*)&Ql[r * VS + c4 * 2] = lo;
    }

    float l0 = 0.f, l1 = 0.f;
    float o[4][4];
    #pragma unroll
    for (int ni = 0; ni < 4; ni++)
        #pragma unroll
        for (int e = 0; e < 4; e++) o[ni][e] = 0.f;

    const int r0 = mw * 16 + g;          // this thread's S/O rows: r0, r0+8
    __syncthreads();

    for (int n0 = 0; n0 < B2; n0 += 64) {
        // K tile [key][d], split
        #pragma unroll
        for (int p = 0; p < 4; p++) {
            int idx = tid + p * 256;
            int r = idx >> 4, c4 = idx & 15;
            float4 v = *(const float4*)(K + (size_t)(n0 + r) * D + h * HD + c4 * 4);
            uint2 hi, lo; split4(v, hi, lo);
            *(uint2*)&Kh[r * VS + c4 * 2] = hi;
            *(uint2*)&Kl[r * VS + c4 * 2] = lo;
        }
        // V tile transposed -> [d][key], split, 2-byte stores
        {
            __nv_bfloat16* Vhh = (__nv_bfloat16*)Vh;
            __nv_bfloat16* Vlh = (__nv_bfloat16*)Vl;
            #pragma unroll
            for (int p = 0; p < 4; p++) {
                int idx = tid + p * 256;
                int r = idx >> 4, c = (idx & 15) * 4;   // key r, dims c..c+3
                float4 v = *(const float4*)(V + (size_t)(n0 + r) * D + h * HD + c);
                float xs[4] = {v.x, v.y, v.z, v.w};
                #pragma unroll
                for (int j = 0; j < 4; j++) {
                    __nv_bfloat16 hb = __float2bfloat16(xs[j]);
                    float rr = xs[j] - __bfloat162float(hb);
                    __nv_bfloat16 lb = __float2bfloat16(rr);
                    Vhh[(c + j) * (2 * VS) + r] = hb;
                    Vlh[(c + j) * (2 * VS) + r] = lb;
                }
            }
        }
        __syncthreads();

        // S = Q . K^T  (bf16x3)
        float s[4][4];
        #pragma unroll
        for (int ni = 0; ni < 4; ni++)
            #pragma unroll
            for (int e = 0; e < 4; e++) s[ni][e] = 0.f;

        #pragma unroll
        for (int ks = 0; ks < 4; ks++) {
            int kw = ks * 8;
            uint32_t ah[4], al[4];
            ah[0] = Qh[r0 * VS + kw + t];
            ah[1] = Qh[(r0 + 8) * VS + kw + t];
            ah[2] = Qh[r0 * VS + kw + t + 4];
            ah[3] = Qh[(r0 + 8) * VS + kw + t + 4];
            al[0] = Ql[r0 * VS + kw + t];
            al[1] = Ql[(r0 + 8) * VS + kw + t];
            al[2] = Ql[r0 * VS + kw + t + 4];
            al[3] = Ql[(r0 + 8) * VS + kw + t + 4];
            #pragma unroll
            for (int ni = 0; ni < 4; ni++) {
                int n = nw * 32 + ni * 8 + g;
                uint32_t bh[2], bl[2];
                bh[0] = Kh[n * VS + kw + t];
                bh[1] = Kh[n * VS + kw + t + 4];
                bl[0] = Kl[n * VS + kw + t];
                bl[1] = Kl[n * VS + kw + t + 4];
                mma_bf16(s[ni], ah, bh);
                mma_bf16(s[ni], ah, bl);
                mma_bf16(s[ni], al, bh);
            }
        }

        // exp (no max needed) + row-sum partials + split/store P
        float rs0 = 0.f, rs1 = 0.f;
        #pragma unroll
        for (int ni = 0; ni < 4; ni++) {
            float p0 = __expf(s[ni][0] * invt);
            float p1 = __expf(s[ni][1] * invt);
            float p2 = __expf(s[ni][2] * invt);
            float p3 = __expf(s[ni][3] * invt);
            rs0 += p0 + p1; rs1 += p2 + p3;
            int wp = nw * 16 + ni * 4 + t;       // word index (pairs along key)
            uint32_t hi, lo;
            split2(p0, p1, hi, lo);
            Ph[r0 * VS + wp] = hi; Pl[r0 * VS + wp] = lo;
            split2(p2, p3, hi, lo);
            Ph[(r0 + 8) * VS + wp] = hi; Pl[(r0 + 8) * VS + wp] = lo;
        }
        rs0 += __shfl_xor_sync(0xffffffffu, rs0, 1);
        rs0 += __shfl_xor_sync(0xffffffffu, rs0, 2);
        rs1 += __shfl_xor_sync(0xffffffffu, rs1, 1);
        rs1 += __shfl_xor_sync(0xffffffffu, rs1, 2);
        if (t == 0) {
            part[w * 16 + g]     = rs0;
            part[w * 16 + g + 8] = rs1;
        }
        __syncthreads();

        // O += P . V  (bf16x3)
        #pragma unroll
        for (int ks = 0; ks < 4; ks++) {
            int kw = ks * 8;
            uint32_t ah[4], al[4];
            ah[0] = Ph[r0 * VS + kw + t];
            ah[1] = Ph[(r0 + 8) * VS + kw + t];
            ah[2] = Ph[r0 * VS + kw + t + 4];
            ah[3] = Ph[(r0 + 8) * VS + kw + t + 4];
            al[0] = Pl[r0 * VS + kw + t];
            al[1] = Pl[(r0 + 8) * VS + kw + t];
            al[2] = Pl[r0 * VS + kw + t + 4];
            al[3] = Pl[(r0 + 8) * VS + kw + t + 4];
            #pragma unroll
            for (int ni = 0; ni < 4; ni++) {
                int n = nw * 32 + ni * 8 + g;
                uint32_t bh[2], bl[2];
                bh[0] = Vh[n * VS + kw + t];
                bh[1] = Vh[n * VS + kw + t + 4];
                bl[0] = Vl[n * VS + kw + t];
                bl[1] = Vl[n * VS + kw + t + 4];
                mma_bf16(o[ni], ah, bh);
                mma_bf16(o[ni], ah, bl);
                mma_bf16(o[ni], al, bh);
            }
        }

        // accumulate row sums (both nw-warps' partials for our rows)
        l0 += part[(2 * mw) * 16 + g]     + part[(2 * mw + 1) * 16 + g];
        l1 += part[(2 * mw) * 16 + g + 8] + part[(2 * mw + 1) * 16 + g + 8];
        __syncthreads();
    }

    // epilogue
    float i0 = 1.0f / l0, i1 = 1.0f / l1;
    #pragma unroll
    for (int ni = 0; ni < 4; ni++) {
        int c = h * HD + nw * 32 + ni * 8 + 2 * t;
        int gr0 = q0 + r0;
        *(float2*)&O[(size_t)gr0 * D + c] =
            make_float2(o[ni][0] * i0, o[ni][1] * i0);
        *(float2*)&O[(size_t)(gr0 + 8) * D + c] =
            make_float2(o[ni][2] * i1, o[ni][3] * i1);
    }
}

// ---------------------------------------------------------------------------
// Full-row L2 norm of X[2048, 768], in place.
// ---------------------------------------------------------------------------
__global__ __launch_bounds__(256) void rownorm_kernel(float* __restrict__ X)
{
    const int row = blockIdx.x;
    const int t = threadIdx.x;
    float* xr = X + (size_t)row * D;
    float s = 0.f;
    for (int i = t; i < D; i += 256) { float v = xr[i]; s += v * v; }
    #pragma unroll
    for (int o = 16; o; o >>= 1) s += __shfl_xor_sync(0xffffffffu, s, o);
    __shared__ float red[8];
    if ((t & 31) == 0) red[t >> 5] = s;
    __syncthreads();
    float tot = 0.f;
    #pragma unroll
    for (int i = 0; i < 8; i++) tot += red[i];
    float scale = 1.0f / fmaxf(sqrtf(tot), 1e-12f);
    for (int i = t; i < D; i += 256) xr[i] *= scale;
}

// ---------------------------------------------------------------------------
extern "C" void kernel_launch(void* const* d_in, const int* in_sizes, int n_in,
                              void* d_out, int out_size)
{
    (void)in_sizes; (void)n_in; (void)out_size;
    const float* x1 = (const float*)d_in[0];
    const float* x2 = (const float*)d_in[1];
    const float* Wq = (const float*)d_in[2];
    const float* Wk = (const float*)d_in[3];
    const float* Wv = (const float*)d_in[4];
    const float* Wo = (const float*)d_in[5];
    const void*  invt = d_in[6];
    float* out = (float*)d_out;

    void *pQ, *pK, *pV, *pO;
    cudaGetSymbolAddress(&pQ, g_Q);
    cudaGetSymbolAddress(&pK, g_K);
    cudaGetSymbolAddress(&pV, g_V);
    cudaGetSymbolAddress(&pO, g_O);

    // Projections (bf16x3 tensor path, ~fp32-accurate)
    gemm_b16x3_kernel<<<dim3(D/128, B1/128), 256>>>(x1, Wq, (float*)pQ, B1, D, D);
    gemm_b16x3_kernel<<<dim3(D/128, B2/128), 256>>>(x2, Wk, (float*)pK, B2, D, D);
    gemm_b16x3_kernel<<<dim3(D/128, B2/128), 256>>>(x2, Wv, (float*)pV, B2, D, D);

    // Per-head cosine normalization
    headnorm_kernel<<<B1, 768>>>((float*)pQ);
    headnorm_kernel<<<B2, 768>>>((float*)pK);

    // Flash attention (bf16x3 tensor path)
    const int smem_bytes = (8 * 64 * VS + 128) * sizeof(uint32_t);  // 74240 B
    cudaFuncSetAttribute(attn_kernel,
                         cudaFuncAttributeMaxDynamicSharedMemorySize, smem_bytes);
    attn_kernel<<<dim3(B1/64, H), 256, smem_bytes>>>(
        (float*)pQ, (float*)pK, (float*)pV, (float*)pO, invt);

    // Output projection into d_out, then in-place row norm
    gemm_b16x3_kernel<<<dim3(D/128, B1/128), 256>>>((float*)pO, Wo, out, B1, D, D);
    rownorm_kernel<<<B1, 256>>>(out);
}

// round 4
// speedup vs baseline: 2.5248x; 1.3906x over previous
#include <cuda_runtime.h>
#include <cuda_fp16.h>
#include <math.h>
#include <stdint.h>

#define D   768
#define H   12
#define HD  64
#define B1  2048
#define B2  8192

// Scratch (allocation-free rule: __device__ globals)
__device__ float g_Q[B1 * D];
__device__ float g_K[B2 * D];
__device__ float g_V[B2 * D];
__device__ float g_O[B1 * D];

__device__ __forceinline__ float decode_scalar(const void* p) {
    int iv = *(const int*)p;
    if (iv >= -1000000 && iv <= 1000000) return (float)iv;
    return *(const float*)p;
}

// Split two floats into packed fp16x2 hi + lo (residual) words.
// Word layout: low 16 bits = element 0, high 16 bits = element 1.
__device__ __forceinline__ void split2h(float x0, float x1,
                                        uint32_t& hi, uint32_t& lo) {
    __half2 h = __floats2half2_rn(x0, x1);
    float r0 = x0 - __low2float(h);
    float r1 = x1 - __high2float(h);
    __half2 l = __floats2half2_rn(r0, r1);
    hi = *reinterpret_cast<uint32_t*>(&h);
    lo = *reinterpret_cast<uint32_t*>(&l);
}

__device__ __forceinline__ uint32_t pack2h(float x0, float x1) {
    __half2 h = __floats2half2_rn(x0, x1);
    return *reinterpret_cast<uint32_t*>(&h);
}

__device__ __forceinline__ void split4h(float4 v, uint2& hi, uint2& lo) {
    split2h(v.x, v.y, hi.x, lo.x);
    split2h(v.z, v.w, hi.y, lo.y);
}

// m16n8k16 fp16 mma, fp32 accumulate
__device__ __forceinline__ void mma_f16(float c[4], const uint32_t a[4],
                                        const uint32_t b[2]) {
    asm volatile(
        "mma.sync.aligned.m16n8k16.row.col.f32.f16.f16.f32 "
        "{%0,%1,%2,%3}, {%4,%5,%6,%7}, {%8,%9}, {%0,%1,%2,%3};"
        : "+f"(c[0]), "+f"(c[1]), "+f"(c[2]), "+f"(c[3])
        : "r"(a[0]), "r"(a[1]), "r"(a[2]), "r"(a[3]), "r"(b[0]), "r"(b[1]));
}

// ---------------------------------------------------------------------------
// C[M,N] = A[M,K] * B[N,K]^T via fp16x3 emulated fp32 mma.
// Block tile 128x128, 8 warps (2x4), warp tile 64x32. K chunk 32 floats.
// ---------------------------------------------------------------------------
#define WS 18   // words per 32-float row chunk (16 + 2 pad)
__global__ __launch_bounds__(256) void gemm_f16x3_kernel(
    const float* __restrict__ A, const float* __restrict__ B,
    float* __restrict__ C, int M, int N, int K)
{
    __shared__ uint32_t Ah[128 * WS], Al[128 * WS];
    __shared__ uint32_t Bh[128 * WS], Bl[128 * WS];

    const int tid = threadIdx.x;
    const int w = tid >> 5, lane = tid & 31;
    const int g = lane >> 2, t = lane & 3;
    const int mw = w >> 2, nw = w & 3;      // 2 x 4 warp grid
    const int m0 = blockIdx.y * 128, n0 = blockIdx.x * 128;

    float acc[4][4][4];
    #pragma unroll
    for (int mi = 0; mi < 4; mi++)
        #pragma unroll
        for (int ni = 0; ni < 4; ni++)
            #pragma unroll
            for (int e = 0; e < 4; e++) acc[mi][ni][e] = 0.f;

    for (int k0 = 0; k0 < K; k0 += 32) {
        #pragma unroll
        for (int p = 0; p < 4; p++) {
            int idx = tid + p * 256;        // 1024 float4 = 128 rows x 8
            int r = idx >> 3, c4 = idx & 7;
            float4 v = *(const float4*)(A + (size_t)(m0 + r) * K + k0 + c4 * 4);
            uint2 hi, lo; split4h(v, hi, lo);
            *(uint2*)&Ah[r * WS + c4 * 2] = hi;
            *(uint2*)&Al[r * WS + c4 * 2] = lo;
        }
        #pragma unroll
        for (int p = 0; p < 4; p++) {
            int idx = tid + p * 256;
            int r = idx >> 3, c4 = idx & 7;
            float4 v = *(const float4*)(B + (size_t)(n0 + r) * K + k0 + c4 * 4);
            uint2 hi, lo; split4h(v, hi, lo);
            *(uint2*)&Bh[r * WS + c4 * 2] = hi;
            *(uint2*)&Bl[r * WS + c4 * 2] = lo;
        }
        __syncthreads();

        #pragma unroll
        for (int ks = 0; ks < 2; ks++) {
            int kw = ks * 8;
            uint32_t ah[4][4], al[4][4];
            #pragma unroll
            for (int mi = 0; mi < 4; mi++) {
                int r = mw * 64 + mi * 16 + g;
                ah[mi][0] = Ah[r * WS + kw + t];
                ah[mi][1] = Ah[(r + 8) * WS + kw + t];
                ah[mi][2] = Ah[r * WS + kw + t + 4];
                ah[mi][3] = Ah[(r + 8) * WS + kw + t + 4];
                al[mi][0] = Al[r * WS + kw + t];
                al[mi][1] = Al[(r + 8) * WS + kw + t];
                al[mi][2] = Al[r * WS + kw + t + 4];
                al[mi][3] = Al[(r + 8) * WS + kw + t + 4];
            }
            #pragma unroll
            for (int ni = 0; ni < 4; ni++) {
                int n = nw * 32 + ni * 8 + g;
                uint32_t bh[2], bl[2];
                bh[0] = Bh[n * WS + kw + t];
                bh[1] = Bh[n * WS + kw + t + 4];
                bl[0] = Bl[n * WS + kw + t];
                bl[1] = Bl[n * WS + kw + t + 4];
                #pragma unroll
                for (int mi = 0; mi < 4; mi++) {
                    mma_f16(acc[mi][ni], ah[mi], bh);
                    mma_f16(acc[mi][ni], ah[mi], bl);
                    mma_f16(acc[mi][ni], al[mi], bh);
                }
            }
        }
        __syncthreads();
    }

    #pragma unroll
    for (int mi = 0; mi < 4; mi++) {
        int r0 = m0 + mw * 64 + mi * 16 + g;
        #pragma unroll
        for (int ni = 0; ni < 4; ni++) {
            int c = n0 + nw * 32 + ni * 8 + 2 * t;
            *(float2*)&C[(size_t)r0 * N + c]       = make_float2(acc[mi][ni][0], acc[mi][ni][1]);
            *(float2*)&C[(size_t)(r0 + 8) * N + c] = make_float2(acc[mi][ni][2], acc[mi][ni][3]);
        }
    }
}

// ---------------------------------------------------------------------------
// Per-head L2 norm: X[rows, 768], 64-wide head chunks.
// ---------------------------------------------------------------------------
__global__ __launch_bounds__(768) void headnorm_kernel(float* __restrict__ X)
{
    const int row = blockIdx.x;
    const int t = threadIdx.x;
    float v = X[(size_t)row * D + t];
    float s = v * v;
    #pragma unroll
    for (int o = 16; o; o >>= 1) s += __shfl_xor_sync(0xffffffffu, s, o);
    __shared__ float ws[24];
    if ((t & 31) == 0) ws[t >> 5] = s;
    __syncthreads();
    int head = t >> 6;
    float sum = ws[head * 2] + ws[head * 2 + 1];
    float scale = 1.0f / fmaxf(sqrtf(sum), 1e-12f);
    X[(size_t)row * D + t] = v * scale;
}

// ---------------------------------------------------------------------------
// Flash attention, fp16 mma with selective emulation:
//   S = (Qh + Ql) . Kh^T        (2 mmas per fragment; K hi-only)
//   P stored as fp16 of p*2^-14 (power-of-2 scale, exact; undone in epilogue)
//   O += P . Vh^T               (1 mma; V hi-only)
// No max subtraction (logits bounded by |invt|; p summed in fp32).
// Block: 64 q rows x 1 head, 8 warps in 4x2 grid over 64x64 S tile.
// ---------------------------------------------------------------------------
#define VS 36   // words per 64-float row (32 + 4 pad)
#define PSCALE   6.103515625e-05f   // 2^-14
#define PUNSCALE 16384.0f           // 2^14
__global__ __launch_bounds__(256) void attn_kernel(
    const float* __restrict__ Q, const float* __restrict__ K,
    const float* __restrict__ V, float* __restrict__ O,
    const void* __restrict__ invt_raw)
{
    extern __shared__ uint32_t sm[];
    uint32_t* Qh = sm;                 // [64 q][VS]  fp16 pairs along d
    uint32_t* Ql = Qh + 64 * VS;
    uint32_t* Kh = Ql + 64 * VS;       // [64 key][VS] pairs along d (hi only)
    uint32_t* Vt = Kh + 64 * VS;       // [64 d][VS] pairs along key (hi only)
    uint32_t* Ph = Vt + 64 * VS;       // [64 q][VS] pairs along key (scaled)
    float*    part = (float*)(Ph + 64 * VS);   // [8][16] row-sum partials

    const int tid = threadIdx.x;
    const int w = tid >> 5, lane = tid & 31;
    const int g = lane >> 2, t = lane & 3;
    const int mw = w >> 1, nw = w & 1;            // 4 x 2 warp grid
    const int h = blockIdx.y;
    const int q0 = blockIdx.x * 64;
    const float invt = decode_scalar(invt_raw);

    // Load + split Q tile [q][d]
    #pragma unroll
    for (int p = 0; p < 4; p++) {
        int idx = tid + p * 256;          // 1024 float4 = 64 rows x 16
        int r = idx >> 4, c4 = idx & 15;
        float4 v = *(const float4*)(Q + (size_t)(q0 + r) * D + h * HD + c4 * 4);
        uint2 hi, lo; split4h(v, hi, lo);
        *(uint2*)&Qh[r * VS + c4 * 2] = hi;
        *(uint2*)&Ql[r * VS + c4 * 2] = lo;
    }

    float l0 = 0.f, l1 = 0.f;
    float o[4][4];
    #pragma unroll
    for (int ni = 0; ni < 4; ni++)
        #pragma unroll
        for (int e = 0; e < 4; e++) o[ni][e] = 0.f;

    const int r0 = mw * 16 + g;          // this thread's S/O rows: r0, r0+8
    __syncthreads();

    for (int n0 = 0; n0 < B2; n0 += 64) {
        // K tile [key][d], hi only
        #pragma unroll
        for (int p = 0; p < 4; p++) {
            int idx = tid + p * 256;
            int r = idx >> 4, c4 = idx & 15;
            float4 v = *(const float4*)(K + (size_t)(n0 + r) * D + h * HD + c4 * 4);
            uint2 hi;
            hi.x = pack2h(v.x, v.y);
            hi.y = pack2h(v.z, v.w);
            *(uint2*)&Kh[r * VS + c4 * 2] = hi;
        }
        // V tile transposed -> [d][key], hi only, 2-byte stores
        {
            __half* Vth = (__half*)Vt;
            #pragma unroll
            for (int p = 0; p < 4; p++) {
                int idx = tid + p * 256;
                int r = idx >> 4, c = (idx & 15) * 4;   // key r, dims c..c+3
                float4 v = *(const float4*)(V + (size_t)(n0 + r) * D + h * HD + c);
                Vth[(c + 0) * (2 * VS) + r] = __float2half_rn(v.x);
                Vth[(c + 1) * (2 * VS) + r] = __float2half_rn(v.y);
                Vth[(c + 2) * (2 * VS) + r] = __float2half_rn(v.z);
                Vth[(c + 3) * (2 * VS) + r] = __float2half_rn(v.w);
            }
        }
        __syncthreads();

        // S = (Qh + Ql) . Kh^T
        float s[4][4];
        #pragma unroll
        for (int ni = 0; ni < 4; ni++)
            #pragma unroll
            for (int e = 0; e < 4; e++) s[ni][e] = 0.f;

        #pragma unroll
        for (int ks = 0; ks < 4; ks++) {
            int kw = ks * 8;
            uint32_t ah[4], al[4];
            ah[0] = Qh[r0 * VS + kw + t];
            ah[1] = Qh[(r0 + 8) * VS + kw + t];
            ah[2] = Qh[r0 * VS + kw + t + 4];
            ah[3] = Qh[(r0 + 8) * VS + kw + t + 4];
            al[0] = Ql[r0 * VS + kw + t];
            al[1] = Ql[(r0 + 8) * VS + kw + t];
            al[2] = Ql[r0 * VS + kw + t + 4];
            al[3] = Ql[(r0 + 8) * VS + kw + t + 4];
            #pragma unroll
            for (int ni = 0; ni < 4; ni++) {
                int n = nw * 32 + ni * 8 + g;
                uint32_t bh[2];
                bh[0] = Kh[n * VS + kw + t];
                bh[1] = Kh[n * VS + kw + t + 4];
                mma_f16(s[ni], ah, bh);
                mma_f16(s[ni], al, bh);
            }
        }

        // exp + fp32 row-sum partials + store scaled-fp16 P
        float rs0 = 0.f, rs1 = 0.f;
        #pragma unroll
        for (int ni = 0; ni < 4; ni++) {
            float p0 = __expf(s[ni][0] * invt);
            float p1 = __expf(s[ni][1] * invt);
            float p2 = __expf(s[ni][2] * invt);
            float p3 = __expf(s[ni][3] * invt);
            rs0 += p0 + p1; rs1 += p2 + p3;
            int wp = nw * 16 + ni * 4 + t;       // word index (pairs along key)
            Ph[r0 * VS + wp]       = pack2h(p0 * PSCALE, p1 * PSCALE);
            Ph[(r0 + 8) * VS + wp] = pack2h(p2 * PSCALE, p3 * PSCALE);
        }
        rs0 += __shfl_xor_sync(0xffffffffu, rs0, 1);
        rs0 += __shfl_xor_sync(0xffffffffu, rs0, 2);
        rs1 += __shfl_xor_sync(0xffffffffu, rs1, 1);
        rs1 += __shfl_xor_sync(0xffffffffu, rs1, 2);
        if (t == 0) {
            part[w * 16 + g]     = rs0;
            part[w * 16 + g + 8] = rs1;
        }
        __syncthreads();

        // O += P . Vh^T
        #pragma unroll
        for (int ks = 0; ks < 4; ks++) {
            int kw = ks * 8;
            uint32_t ap[4];
            ap[0] = Ph[r0 * VS + kw + t];
            ap[1] = Ph[(r0 + 8) * VS + kw + t];
            ap[2] = Ph[r0 * VS + kw + t + 4];
            ap[3] = Ph[(r0 + 8) * VS + kw + t + 4];
            #pragma unroll
            for (int ni = 0; ni < 4; ni++) {
                int n = nw * 32 + ni * 8 + g;
                uint32_t bh[2];
                bh[0] = Vt[n * VS + kw + t];
                bh[1] = Vt[n * VS + kw + t + 4];
                mma_f16(o[ni], ap, bh);
            }
        }

        // accumulate row sums (both nw-warps' partials for our rows)
        l0 += part[(2 * mw) * 16 + g]     + part[(2 * mw + 1) * 16 + g];
        l1 += part[(2 * mw) * 16 + g + 8] + part[(2 * mw + 1) * 16 + g + 8];
        __syncthreads();
    }

    // epilogue: undo the 2^-14 P scaling and normalize
    float i0 = PUNSCALE / l0, i1 = PUNSCALE / l1;
    #pragma unroll
    for (int ni = 0; ni < 4; ni++) {
        int c = h * HD + nw * 32 + ni * 8 + 2 * t;
        int gr0 = q0 + r0;
        *(float2*)&O[(size_t)gr0 * D + c] =
            make_float2(o[ni][0] * i0, o[ni][1] * i0);
        *(float2*)&O[(size_t)(gr0 + 8) * D + c] =
            make_float2(o[ni][2] * i1, o[ni][3] * i1);
    }
}

// ---------------------------------------------------------------------------
// Full-row L2 norm of X[2048, 768], in place.
// ---------------------------------------------------------------------------
__global__ __launch_bounds__(256) void rownorm_kernel(float* __restrict__ X)
{
    const int row = blockIdx.x;
    const int t = threadIdx.x;
    float* xr = X + (size_t)row * D;
    float s = 0.f;
    for (int i = t; i < D; i += 256) { float v = xr[i]; s += v * v; }
    #pragma unroll
    for (int o = 16; o; o >>= 1) s += __shfl_xor_sync(0xffffffffu, s, o);
    __shared__ float red[8];
    if ((t & 31) == 0) red[t >> 5] = s;
    __syncthreads();
    float tot = 0.f;
    #pragma unroll
    for (int i = 0; i < 8; i++) tot += red[i];
    float scale = 1.0f / fmaxf(sqrtf(tot), 1e-12f);
    for (int i = t; i < D; i += 256) xr[i] *= scale;
}

// ---------------------------------------------------------------------------
extern "C" void kernel_launch(void* const* d_in, const int* in_sizes, int n_in,
                              void* d_out, int out_size)
{
    (void)in_sizes; (void)n_in; (void)out_size;
    const float* x1 = (const float*)d_in[0];
    const float* x2 = (const float*)d_in[1];
    const float* Wq = (const float*)d_in[2];
    const float* Wk = (const float*)d_in[3];
    const float* Wv = (const float*)d_in[4];
    const float* Wo = (const float*)d_in[5];
    const void*  invt = d_in[6];
    float* out = (float*)d_out;

    void *pQ, *pK, *pV, *pO;
    cudaGetSymbolAddress(&pQ, g_Q);
    cudaGetSymbolAddress(&pK, g_K);
    cudaGetSymbolAddress(&pV, g_V);
    cudaGetSymbolAddress(&pO, g_O);

    // Projections (fp16x3 tensor path, ~fp32-accurate)
    gemm_f16x3_kernel<<<dim3(D/128, B1/128), 256>>>(x1, Wq, (float*)pQ, B1, D, D);
    gemm_f16x3_kernel<<<dim3(D/128, B2/128), 256>>>(x2, Wk, (float*)pK, B2, D, D);
    gemm_f16x3_kernel<<<dim3(D/128, B2/128), 256>>>(x2, Wv, (float*)pV, B2, D, D);

    // Per-head cosine normalization
    headnorm_kernel<<<B1, 768>>>((float*)pQ);
    headnorm_kernel<<<B2, 768>>>((float*)pK);

    // Flash attention (fp16 selective-emulation tensor path)
    const int smem_bytes = (5 * 64 * VS + 128) * sizeof(uint32_t);  // 46592 B
    cudaFuncSetAttribute(attn_kernel,
                         cudaFuncAttributeMaxDynamicSharedMemorySize, smem_bytes);
    attn_kernel<<<dim3(B1/64, H), 256, smem_bytes>>>(
        (float*)pQ, (float*)pK, (float*)pV, (float*)pO, invt);

    // Output projection into d_out, then in-place row norm
    gemm_f16x3_kernel<<<dim3(D/128, B1/128), 256>>>((float*)pO, Wo, out, B1, D, D);
    rownorm_kernel<<<B1, 256>>>(out);
}

// round 7
// speedup vs baseline: 3.7228x; 1.4745x over previous
#include <cuda_runtime.h>
#include <cuda_fp16.h>
#include <math.h>
#include <stdint.h>

#define D   768
#define H   12
#define HD  64
#define B1  2048
#define B2  8192

// Scratch (allocation-free rule: __device__ globals)
__device__ float g_Q[B1 * D];
__device__ float g_K[B2 * D];
__device__ float g_V[B2 * D];
__device__ float g_O[B1 * D];

__device__ __forceinline__ float decode_scalar(const void* p) {
    int iv = *(const int*)p;
    if (iv >= -1000000 && iv <= 1000000) return (float)iv;
    return *(const float*)p;
}

// ---- fp16 split helpers ----------------------------------------------------
__device__ __forceinline__ void split2h(float x0, float x1,
                                        uint32_t& hi, uint32_t& lo) {
    __half2 h = __floats2half2_rn(x0, x1);
    float r0 = x0 - __low2float(h);
    float r1 = x1 - __high2float(h);
    __half2 l = __floats2half2_rn(r0, r1);
    hi = *reinterpret_cast<uint32_t*>(&h);
    lo = *reinterpret_cast<uint32_t*>(&l);
}

__device__ __forceinline__ uint32_t pack2h(float x0, float x1) {
    __half2 h = __floats2half2_rn(x0, x1);
    return *reinterpret_cast<uint32_t*>(&h);
}

__device__ __forceinline__ void split4h(float4 v, uint2& hi, uint2& lo) {
    split2h(v.x, v.y, hi.x, lo.x);
    split2h(v.z, v.w, hi.y, lo.y);
}

// ---- mma + ldmatrix --------------------------------------------------------
__device__ __forceinline__ void mma_f16(float c[4], const uint32_t a[4],
                                        const uint32_t b[2]) {
    asm volatile(
        "mma.sync.aligned.m16n8k16.row.col.f32.f16.f16.f32 "
        "{%0,%1,%2,%3}, {%4,%5,%6,%7}, {%8,%9}, {%0,%1,%2,%3};"
        : "+f"(c[0]), "+f"(c[1]), "+f"(c[2]), "+f"(c[3])
        : "r"(a[0]), "r"(a[1]), "r"(a[2]), "r"(a[3]), "r"(b[0]), "r"(b[1]));
}

__device__ __forceinline__ uint32_t smem_u32(const void* p) {
    uint32_t a;
    asm("{ .reg .u64 t; cvta.to.shared.u64 t, %1; cvt.u32.u64 %0, t; }"
        : "=r"(a) : "l"(p));
    return a;
}

__device__ __forceinline__ void ldsm_x4(uint32_t r[4], uint32_t addr) {
    asm volatile("ldmatrix.sync.aligned.m8n8.x4.shared.b16 {%0,%1,%2,%3}, [%4];"
                 : "=r"(r[0]), "=r"(r[1]), "=r"(r[2]), "=r"(r[3]) : "r"(addr));
}
__device__ __forceinline__ void ldsm_x2(uint32_t r[2], uint32_t addr) {
    asm volatile("ldmatrix.sync.aligned.m8n8.x2.shared.b16 {%0,%1}, [%2];"
                 : "=r"(r[0]), "=r"(r[1]) : "r"(addr));
}
__device__ __forceinline__ void ldsm_x2t(uint32_t r[2], uint32_t addr) {
    asm volatile("ldmatrix.sync.aligned.m8n8.x2.trans.shared.b16 {%0,%1}, [%2];"
                 : "=r"(r[0]), "=r"(r[1]) : "r"(addr));
}

// ---------------------------------------------------------------------------
// C[M,N] = A[M,K] * B[N,K]^T via fp16x3 emulated fp32 mma.
// Block tile 128x128, 8 warps (2x4), warp tile 64x32. K chunk 32 floats.
// Double-buffered smem (one bar.sync per chunk), ldmatrix fragment loads.
// Per-stage arrays Ah/Al/Bh/Bl [128][WS] words; WS=20 -> conflict-free LDSM.
// ---------------------------------------------------------------------------
#define WS   20
#define ARR  (128 * WS)        // 2560 words per array
#define STG  (4 * ARR)         // 10240 words per stage
__global__ __launch_bounds__(256) void gemm_f16x3_kernel(
    const float* __restrict__ A, const float* __restrict__ B,
    float* __restrict__ C, int M, int N, int K)
{
    extern __shared__ uint32_t S[];
    const uint32_t sb = smem_u32(S);

    const int tid = threadIdx.x;
    const int w = tid >> 5, lane = tid & 31;
    const int g = lane >> 2, t = lane & 3;
    const int mw = w >> 2, nw = w & 3;      // 2 x 4 warp grid
    const int m0 = blockIdx.y * 128, n0 = blockIdx.x * 128;

    float acc[4][4][4];
    #pragma unroll
    for (int mi = 0; mi < 4; mi++)
        #pragma unroll
        for (int ni = 0; ni < 4; ni++)
            #pragma unroll
            for (int e = 0; e < 4; e++) acc[mi][ni][e] = 0.f;

    // precomputed ldmatrix lane-address offsets (in words)
    const int aoff = (mw * 64 + (lane & 15)) * WS + (lane >> 4) * 4;
    const int boff = (nw * 32 + (lane & 7)) * WS + ((lane >> 3) & 1) * 4;

    const int NCH = K >> 5;
    for (int ch = 0; ch < NCH; ch++) {
        uint32_t* st = S + (ch & 1) * STG;
        // fill stage: A,B chunk (128 rows x 32 floats each), split hi/lo
        #pragma unroll
        for (int p = 0; p < 4; p++) {
            int idx = tid + p * 256;          // 1024 float4
            int r = idx >> 3, c4 = idx & 7;
            float4 va = *(const float4*)(A + (size_t)(m0 + r) * K + ch * 32 + c4 * 4);
            uint2 hi, lo; split4h(va, hi, lo);
            *(uint2*)&st[r * WS + c4 * 2] = hi;
            *(uint2*)&st[ARR + r * WS + c4 * 2] = lo;
        }
        #pragma unroll
        for (int p = 0; p < 4; p++) {
            int idx = tid + p * 256;
            int r = idx >> 3, c4 = idx & 7;
            float4 vb = *(const float4*)(B + (size_t)(n0 + r) * K + ch * 32 + c4 * 4);
            uint2 hi, lo; split4h(vb, hi, lo);
            *(uint2*)&st[2 * ARR + r * WS + c4 * 2] = hi;
            *(uint2*)&st[3 * ARR + r * WS + c4 * 2] = lo;
        }
        __syncthreads();   // fence: stage stores visible; prior-stage LDSM done

        const uint32_t sbase = sb + (ch & 1) * (STG * 4);
        #pragma unroll
        for (int ks = 0; ks < 2; ks++) {
            int kw = ks * 8;
            uint32_t ah[4][4], al[4][4];
            #pragma unroll
            for (int mi = 0; mi < 4; mi++) {
                uint32_t ra = sbase + (aoff + mi * 16 * WS + kw) * 4;
                ldsm_x4(ah[mi], ra);
                ldsm_x4(al[mi], ra + ARR * 4);
            }
            #pragma unroll
            for (int ni = 0; ni < 4; ni++) {
                uint32_t rb = sbase + (2 * ARR + boff + ni * 8 * WS + kw) * 4;
                uint32_t bh[2], bl[2];
                ldsm_x2(bh, rb);
                ldsm_x2(bl, rb + ARR * 4);
                #pragma unroll
                for (int mi = 0; mi < 4; mi++) {
                    mma_f16(acc[mi][ni], ah[mi], bh);
                    mma_f16(acc[mi][ni], ah[mi], bl);
                    mma_f16(acc[mi][ni], al[mi], bh);
                }
            }
        }
        // no trailing sync: next chunk writes the other stage
    }

    #pragma unroll
    for (int mi = 0; mi < 4; mi++) {
        int r0 = m0 + mw * 64 + mi * 16 + g;
        #pragma unroll
        for (int ni = 0; ni < 4; ni++) {
            int c = n0 + nw * 32 + ni * 8 + 2 * t;
            *(float2*)&C[(size_t)r0 * N + c]       = make_float2(acc[mi][ni][0], acc[mi][ni][1]);
            *(float2*)&C[(size_t)(r0 + 8) * N + c] = make_float2(acc[mi][ni][2], acc[mi][ni][3]);
        }
    }
}

// ---------------------------------------------------------------------------
// Per-head L2 norm: X[rows, 768], 64-wide head chunks.
// ---------------------------------------------------------------------------
__global__ __launch_bounds__(768) void headnorm_kernel(float* __restrict__ X)
{
    const int row = blockIdx.x;
    const int t = threadIdx.x;
    float v = X[(size_t)row * D + t];
    float s = v * v;
    #pragma unroll
    for (int o = 16; o; o >>= 1) s += __shfl_xor_sync(0xffffffffu, s, o);
    __shared__ float ws[24];
    if ((t & 31) == 0) ws[t >> 5] = s;
    __syncthreads();
    int head = t >> 6;
    float sum = ws[head * 2] + ws[head * 2 + 1];
    float scale = 1.0f / fmaxf(sqrtf(sum), 1e-12f);
    X[(size_t)row * D + t] = v * scale;
}

// ---------------------------------------------------------------------------
// Flash attention, fp16 mma with selective emulation (numerics == R4):
//   S = (Qh + Ql) . Kh^T ; P as fp16 of p*2^-14 ; O += P . V^T
// ldmatrix fragment loads; V kept in natural [key][d] layout, transposed
// inside ldmatrix.x2.trans. Block: 64 q x 1 head, 8 warps (4x2 over S).
// ---------------------------------------------------------------------------
#define VS 36   // words per 64-half row (32 + 4 pad)
#define PSCALE   6.103515625e-05f   // 2^-14
#define PUNSCALE 16384.0f           // 2^14
__global__ __launch_bounds__(256) void attn_kernel(
    const float* __restrict__ Q, const float* __restrict__ K,
    const float* __restrict__ V, float* __restrict__ O,
    const void* __restrict__ invt_raw)
{
    extern __shared__ uint32_t sm[];
    uint32_t* Qh = sm;                 // [64 q][VS] pairs along d
    uint32_t* Ql = Qh + 64 * VS;
    uint32_t* Kh = Ql + 64 * VS;       // [64 key][VS] pairs along d
    uint32_t* Vh = Kh + 64 * VS;       // [64 key][VS] pairs along d (natural!)
    uint32_t* Ph = Vh + 64 * VS;       // [64 q][VS] pairs along key (scaled)
    float*    part = (float*)(Ph + 64 * VS);   // [8][16] row-sum partials

    const uint32_t sb = smem_u32(sm);
    const uint32_t QhO = 0, QlO = 64 * VS * 4, KhO = 2 * 64 * VS * 4,
                   VhO = 3 * 64 * VS * 4, PhO = 4 * 64 * VS * 4;

    const int tid = threadIdx.x;
    const int w = tid >> 5, lane = tid & 31;
    const int g = lane >> 2, t = lane & 3;
    const int mw = w >> 1, nw = w & 1;            // 4 x 2 warp grid
    const int h = blockIdx.y;
    const int q0 = blockIdx.x * 64;
    const float invt = decode_scalar(invt_raw);

    // ldmatrix lane-address offsets (words)
    const int aoff  = (mw * 16 + (lane & 15)) * VS + (lane >> 4) * 4;  // A frags
    const int boff  = (nw * 32 + (lane & 7)) * VS + ((lane >> 3) & 1) * 4; // K frags
    const int voffr = (lane & 7) + ((lane >> 3) & 1) * 8;              // V row part

    // Load + split Q tile [q][d]
    #pragma unroll
    for (int p = 0; p < 4; p++) {
        int idx = tid + p * 256;
        int r = idx >> 4, c4 = idx & 15;
        float4 v = *(const float4*)(Q + (size_t)(q0 + r) * D + h * HD + c4 * 4);
        uint2 hi, lo; split4h(v, hi, lo);
        *(uint2*)&Qh[r * VS + c4 * 2] = hi;
        *(uint2*)&Ql[r * VS + c4 * 2] = lo;
    }

    float l0 = 0.f, l1 = 0.f;
    float o[4][4];
    #pragma unroll
    for (int ni = 0; ni < 4; ni++)
        #pragma unroll
        for (int e = 0; e < 4; e++) o[ni][e] = 0.f;

    const int r0 = mw * 16 + g;
    __syncthreads();

    for (int n0 = 0; n0 < B2; n0 += 64) {
        // K tile [key][d] hi, V tile [key][d] hi — both vectorized
        #pragma unroll
        for (int p = 0; p < 4; p++) {
            int idx = tid + p * 256;
            int r = idx >> 4, c4 = idx & 15;
            float4 v = *(const float4*)(K + (size_t)(n0 + r) * D + h * HD + c4 * 4);
            uint2 hi;
            hi.x = pack2h(v.x, v.y);
            hi.y = pack2h(v.z, v.w);
            *(uint2*)&Kh[r * VS + c4 * 2] = hi;
            float4 vv = *(const float4*)(V + (size_t)(n0 + r) * D + h * HD + c4 * 4);
            hi.x = pack2h(vv.x, vv.y);
            hi.y = pack2h(vv.z, vv.w);
            *(uint2*)&Vh[r * VS + c4 * 2] = hi;
        }
        __syncthreads();

        // S = (Qh + Ql) . Kh^T
        float s[4][4];
        #pragma unroll
        for (int ni = 0; ni < 4; ni++)
            #pragma unroll
            for (int e = 0; e < 4; e++) s[ni][e] = 0.f;

        #pragma unroll
        for (int ks = 0; ks < 4; ks++) {
            int kw = ks * 8;
            uint32_t ah[4], al[4];
            ldsm_x4(ah, sb + QhO + (aoff + kw) * 4);
            ldsm_x4(al, sb + QlO + (aoff + kw) * 4);
            #pragma unroll
            for (int ni = 0; ni < 4; ni++) {
                uint32_t bh[2];
                ldsm_x2(bh, sb + KhO + (boff + ni * 8 * VS + kw) * 4);
                mma_f16(s[ni], ah, bh);
                mma_f16(s[ni], al, bh);
            }
        }

        // exp + fp32 row-sum partials + store scaled-fp16 P
        float rs0 = 0.f, rs1 = 0.f;
        #pragma unroll
        for (int ni = 0; ni < 4; ni++) {
            float p0 = __expf(s[ni][0] * invt);
            float p1 = __expf(s[ni][1] * invt);
            float p2 = __expf(s[ni][2] * invt);
            float p3 = __expf(s[ni][3] * invt);
            rs0 += p0 + p1; rs1 += p2 + p3;
            int wp = nw * 16 + ni * 4 + t;
            Ph[r0 * VS + wp]       = pack2h(p0 * PSCALE, p1 * PSCALE);
            Ph[(r0 + 8) * VS + wp] = pack2h(p2 * PSCALE, p3 * PSCALE);
        }
        rs0 += __shfl_xor_sync(0xffffffffu, rs0, 1);
        rs0 += __shfl_xor_sync(0xffffffffu, rs0, 2);
        rs1 += __shfl_xor_sync(0xffffffffu, rs1, 1);
        rs1 += __shfl_xor_sync(0xffffffffu, rs1, 2);
        if (t == 0) {
            part[w * 16 + g]     = rs0;
            part[w * 16 + g + 8] = rs1;
        }
        __syncthreads();

        // O += P . V  (V transposed inside ldmatrix)
        #pragma unroll
        for (int ks = 0; ks < 4; ks++) {
            int kw = ks * 8;
            uint32_t ap[4];
            ldsm_x4(ap, sb + PhO + (aoff + kw) * 4);
            #pragma unroll
            for (int ni = 0; ni < 4; ni++) {
                uint32_t bv[2];
                uint32_t rv = sb + VhO +
                    ((ks * 16 + voffr) * VS + nw * 16 + ni * 4) * 4;
                ldsm_x2t(bv, rv);
                mma_f16(o[ni], ap, bv);
            }
        }

        l0 += part[(2 * mw) * 16 + g]     + part[(2 * mw + 1) * 16 + g];
        l1 += part[(2 * mw) * 16 + g + 8] + part[(2 * mw + 1) * 16 + g + 8];
        __syncthreads();
    }

    float i0 = PUNSCALE / l0, i1 = PUNSCALE / l1;
    #pragma unroll
    for (int ni = 0; ni < 4; ni++) {
        int c = h * HD + nw * 32 + ni * 8 + 2 * t;
        int gr0 = q0 + r0;
        *(float2*)&O[(size_t)gr0 * D + c] =
            make_float2(o[ni][0] * i0, o[ni][1] * i0);
        *(float2*)&O[(size_t)(gr0 + 8) * D + c] =
            make_float2(o[ni][2] * i1, o[ni][3] * i1);
    }
}

// ---------------------------------------------------------------------------
// Full-row L2 norm of X[2048, 768], in place.
// ---------------------------------------------------------------------------
__global__ __launch_bounds__(256) void rownorm_kernel(float* __restrict__ X)
{
    const int row = blockIdx.x;
    const int t = threadIdx.x;
    float* xr = X + (size_t)row * D;
    float s = 0.f;
    for (int i = t; i < D; i += 256) { float v = xr[i]; s += v * v; }
    #pragma unroll
    for (int o = 16; o; o >>= 1) s += __shfl_xor_sync(0xffffffffu, s, o);
    __shared__ float red[8];
    if ((t & 31) == 0) red[t >> 5] = s;
    __syncthreads();
    float tot = 0.f;
    #pragma unroll
    for (int i = 0; i < 8; i++) tot += red[i];
    float scale = 1.0f / fmaxf(sqrtf(tot), 1e-12f);
    for (int i = t; i < D; i += 256) xr[i] *= scale;
}

// ---------------------------------------------------------------------------
extern "C" void kernel_launch(void* const* d_in, const int* in_sizes, int n_in,
                              void* d_out, int out_size)
{
    (void)in_sizes; (void)n_in; (void)out_size;
    const float* x1 = (const float*)d_in[0];
    const float* x2 = (const float*)d_in[1];
    const float* Wq = (const float*)d_in[2];
    const float* Wk = (const float*)d_in[3];
    const float* Wv = (const float*)d_in[4];
    const float* Wo = (const float*)d_in[5];
    const void*  invt = d_in[6];
    float* out = (float*)d_out;

    void *pQ, *pK, *pV, *pO;
    cudaGetSymbolAddress(&pQ, g_Q);
    cudaGetSymbolAddress(&pK, g_K);
    cudaGetSymbolAddress(&pV, g_V);
    cudaGetSymbolAddress(&pO, g_O);

    // Projections (fp16x3, double-buffered, ldmatrix)
    const int gsmem = 2 * STG * 4;   // 81920 B
    cudaFuncSetAttribute(gemm_f16x3_kernel,
                         cudaFuncAttributeMaxDynamicSharedMemorySize, gsmem);
    gemm_f16x3_kernel<<<dim3(D/128, B1/128), 256, gsmem>>>(x1, Wq, (float*)pQ, B1, D, D);
    gemm_f16x3_kernel<<<dim3(D/128, B2/128), 256, gsmem>>>(x2, Wk, (float*)pK, B2, D, D);
    gemm_f16x3_kernel<<<dim3(D/128, B2/128), 256, gsmem>>>(x2, Wv, (float*)pV, B2, D, D);

    // Per-head cosine normalization
    headnorm_kernel<<<B1, 768>>>((float*)pQ);
    headnorm_kernel<<<B2, 768>>>((float*)pK);

    // Flash attention
    const int smem_bytes = (5 * 64 * VS + 128) * sizeof(uint32_t);  // 46592 B
    cudaFuncSetAttribute(attn_kernel,
                         cudaFuncAttributeMaxDynamicSharedMemorySize, smem_bytes);
    attn_kernel<<<dim3(B1/64, H), 256, smem_bytes>>>(
        (float*)pQ, (float*)pK, (float*)pV, (float*)pO, invt);

    // Output projection into d_out, then in-place row norm
    gemm_f16x3_kernel<<<dim3(D/128, B1/128), 256, gsmem>>>((float*)pO, Wo, out, B1, D, D);
    rownorm_kernel<<<B1, 256>>>(out);
}